// round 3
// baseline (speedup 1.0000x reference)
#include <cuda_runtime.h>

#define NN 50000
#define NE 800000
#define DM 64
#define DE 32
#define DH 256
#define NG 64
#define EPSV 1e-5f

// ---------------- scratch (static device arrays; no allocation) ----------------
__device__ __align__(256) float g_Xd[NN * DH];     // h @ msg_w1[0:64]     (dst part)
__device__ __align__(256) float g_Xs[NN * DH];     // h @ msg_w1[64:128]   (src part)
__device__ __align__(256) float g_agg[NN * DM];    // segment-summed messages
__device__ __align__(256) float g_hnew[NN * DM];   // h + dh
__device__ __align__(256) float g_gsum[NG * DM];
__device__ __align__(256) float g_gvar[NG * DM];
__device__ __align__(256) float g_mean[NG * DM];
__device__ __align__(256) float g_rstd[NG * DM];
__device__ __align__(256) float g_gcnt[NG];

__device__ __forceinline__ float silu_f(float x) { return x / (1.f + __expf(-x)); }

__device__ __forceinline__ void fma4(float4& c, float a, const float4& b) {
    c.x = fmaf(a, b.x, c.x);
    c.y = fmaf(a, b.y, c.y);
    c.z = fmaf(a, b.z, c.z);
    c.w = fmaf(a, b.w, c.w);
}

// ---------------- K0: zero scratch ----------------
__global__ void k_zero() {
    int i = blockIdx.x * blockDim.x + threadIdx.x;
    int stride = gridDim.x * blockDim.x;
    for (int j = i; j < NN * DM; j += stride) g_agg[j] = 0.f;
    if (i < NG * DM) { g_gsum[i] = 0.f; g_gvar[i] = 0.f; }
    if (i < NG) g_gcnt[i] = 0.f;
}

// ---------------- K1: per-node precompute Xd, Xs ----------------
// Xd = h @ W1[0:64], Xs = h @ W1[64:128].  Block = 64 nodes, 256 threads.
__global__ __launch_bounds__(256, 1) void k_pre(const float* __restrict__ h,
                                                const float* __restrict__ w1) {
    extern __shared__ float sm[];
    float* As = sm;          // 64 x 65 (padded)
    float* Ws = sm + 4160;   // 64 x 256

    int tid = threadIdx.x;
    int node0 = blockIdx.x * 64;

    for (int idx = tid; idx < 64 * 64; idx += 256) {
        int m = idx >> 6, k = idx & 63;
        int n = node0 + m;
        As[m * 65 + k] = (n < NN) ? h[n * 64 + k] : 0.f;
    }

    int tx = tid & 15, ty = tid >> 4;
    int m0 = ty * 4;

    #pragma unroll 1
    for (int p = 0; p < 2; ++p) {
        __syncthreads();
        for (int idx = tid; idx < 64 * 256; idx += 256)
            Ws[idx] = w1[p * 64 * 256 + idx];
        __syncthreads();

        float4 acc[4][4];
        #pragma unroll
        for (int i = 0; i < 4; i++)
            #pragma unroll
            for (int j = 0; j < 4; j++) acc[i][j] = make_float4(0.f, 0.f, 0.f, 0.f);

        #pragma unroll 4
        for (int k = 0; k < 64; k++) {
            float a[4];
            #pragma unroll
            for (int i = 0; i < 4; i++) a[i] = As[(m0 + i) * 65 + k];
            #pragma unroll
            for (int j = 0; j < 4; j++) {
                float4 w = *(const float4*)&Ws[k * 256 + tx * 4 + 64 * j];
                #pragma unroll
                for (int i = 0; i < 4; i++) fma4(acc[i][j], a[i], w);
            }
        }

        float* out = p ? g_Xs : g_Xd;
        #pragma unroll
        for (int i = 0; i < 4; i++) {
            int n = node0 + m0 + i;
            if (n < NN) {
                #pragma unroll
                for (int j = 0; j < 4; j++)
                    *(float4*)&out[n * 256 + tx * 4 + 64 * j] = acc[i][j];
            }
        }
    }
}

// ---------------- K2: edge MLP + scatter-add (persistent grid) ----------------
// hidden = silu(Xd[dst] + Xs[src] + e@W1c + b1); m = hidden@W2 + b2; agg[dst] += m
__global__ __launch_bounds__(256, 1) void k_edge(const float* __restrict__ ea,
                                                 const int* __restrict__ eidx,
                                                 const float* __restrict__ w1,
                                                 const float* __restrict__ b1,
                                                 const float* __restrict__ w2,
                                                 const float* __restrict__ b2) {
    extern __shared__ float sm[];
    float* W1c = sm;             // 32 x 256  = 8192
    float* W2s = sm + 8192;      // 256 x 64  = 16384
    float* B1  = sm + 24576;     // 256
    float* B2  = sm + 24832;     // 64
    float* EA  = sm + 24896;     // 64 x 33   = 2112
    float* Hs  = sm + 27008;     // 64 x 260  = 16640
    int*   SD  = (int*)(sm + 43648);  // 64
    int*   SS  = (int*)(sm + 43712);  // 64

    int tid = threadIdx.x;
    for (int idx = tid; idx < 32 * 256; idx += 256) W1c[idx] = w1[128 * 256 + idx];
    for (int idx = tid; idx < 256 * 64; idx += 256) W2s[idx] = w2[idx];
    if (tid < 256) B1[tid] = b1[tid];
    if (tid < 64)  B2[tid] = b2[tid];

    int tx = tid & 15, ty = tid >> 4;
    int m0 = ty * 4;
    int lane = tid & 31, wrp = tid >> 5;

    for (int t = blockIdx.x; t < NE / 64; t += gridDim.x) {
        int e0 = t * 64;
        __syncthreads();  // protect smem reuse across tiles (and initial loads)

        if (tid < 64) {
            SS[tid] = eidx[e0 + tid];        // row 0 = src
            SD[tid] = eidx[NE + e0 + tid];   // row 1 = dst
        }
        for (int idx = tid; idx < 64 * 32; idx += 256) {
            int m = idx >> 5, k = idx & 31;
            EA[m * 33 + k] = ea[e0 * 32 + idx];
        }
        __syncthreads();

        // GEMM1: C[64,256] = EA[64,32] @ W1c[32,256]
        float4 acc[4][4];
        #pragma unroll
        for (int i = 0; i < 4; i++)
            #pragma unroll
            for (int j = 0; j < 4; j++) acc[i][j] = make_float4(0.f, 0.f, 0.f, 0.f);

        #pragma unroll 4
        for (int k = 0; k < 32; k++) {
            float a[4];
            #pragma unroll
            for (int i = 0; i < 4; i++) a[i] = EA[(m0 + i) * 33 + k];
            #pragma unroll
            for (int j = 0; j < 4; j++) {
                float4 w = *(const float4*)&W1c[k * 256 + tx * 4 + 64 * j];
                #pragma unroll
                for (int i = 0; i < 4; i++) fma4(acc[i][j], a[i], w);
            }
        }
        #pragma unroll
        for (int i = 0; i < 4; i++)
            #pragma unroll
            for (int j = 0; j < 4; j++)
                *(float4*)&Hs[(m0 + i) * 260 + tx * 4 + 64 * j] = acc[i][j];
        __syncthreads();

        // gather Xd[dst] + Xs[src] + b1, silu, store back. Warp per 8 rows.
        #pragma unroll 2
        for (int r = 0; r < 8; r++) {
            int m = wrp * 8 + r;
            int dn = SD[m], sn = SS[m];
            #pragma unroll
            for (int j2 = 0; j2 < 2; j2++) {
                int n = lane * 4 + 128 * j2;
                float4 xd = *(const float4*)&g_Xd[dn * 256 + n];
                float4 xs = *(const float4*)&g_Xs[sn * 256 + n];
                float4 hv = *(float4*)&Hs[m * 260 + n];
                float4 bb = *(const float4*)&B1[n];
                hv.x = silu_f(hv.x + xd.x + xs.x + bb.x);
                hv.y = silu_f(hv.y + xd.y + xs.y + bb.y);
                hv.z = silu_f(hv.z + xd.z + xs.z + bb.z);
                hv.w = silu_f(hv.w + xd.w + xs.w + bb.w);
                *(float4*)&Hs[m * 260 + n] = hv;
            }
        }
        __syncthreads();

        // GEMM2: m[64,64] = H[64,256] @ W2[256,64]
        float4 c2[4];
        #pragma unroll
        for (int i = 0; i < 4; i++) c2[i] = make_float4(0.f, 0.f, 0.f, 0.f);

        #pragma unroll 2
        for (int k0 = 0; k0 < 256; k0 += 4) {
            float ha[4][4];
            #pragma unroll
            for (int i = 0; i < 4; i++) {
                float4 tq = *(const float4*)&Hs[(m0 + i) * 260 + k0];
                ha[i][0] = tq.x; ha[i][1] = tq.y; ha[i][2] = tq.z; ha[i][3] = tq.w;
            }
            #pragma unroll
            for (int kk = 0; kk < 4; kk++) {
                float4 w = *(const float4*)&W2s[(k0 + kk) * 64 + tx * 4];
                #pragma unroll
                for (int i = 0; i < 4; i++) fma4(c2[i], ha[i][kk], w);
            }
        }

        float4 bb2 = *(const float4*)&B2[tx * 4];
        #pragma unroll
        for (int i = 0; i < 4; i++) {
            int dn = SD[m0 + i];
            float4 v;
            v.x = c2[i].x + bb2.x; v.y = c2[i].y + bb2.y;
            v.z = c2[i].z + bb2.z; v.w = c2[i].w + bb2.w;
            float* p = &g_agg[dn * 64 + tx * 4];
            asm volatile("red.global.add.v4.f32 [%0], {%1, %2, %3, %4};"
                         :: "l"(p), "f"(v.x), "f"(v.y), "f"(v.z), "f"(v.w)
                         : "memory");
        }
    }
}

// ---------------- K3: node update MLP, h_new = h + dh ----------------
__global__ __launch_bounds__(256, 1) void k_node(const float* __restrict__ h,
                                                 const float* __restrict__ u1,
                                                 const float* __restrict__ ub1,
                                                 const float* __restrict__ u2,
                                                 const float* __restrict__ ub2) {
    extern __shared__ float sm[];
    float* U2 = sm;              // 256 x 64 = 16384
    float* WC = sm + 16384;      // 32 x 256 = 8192 (streamed chunks of upd_w1)
    float* B1 = sm + 24576;      // 256
    float* B2 = sm + 24832;      // 64
    float* A  = sm + 24896;      // 64 x 129 = 8256
    float* Hs = sm + 33152;      // 64 x 260 = 16640

    int tid = threadIdx.x;
    int node0 = blockIdx.x * 64;

    for (int idx = tid; idx < 256 * 64; idx += 256) U2[idx] = u2[idx];
    if (tid < 256) B1[tid] = ub1[tid];
    if (tid < 64)  B2[tid] = ub2[tid];

    for (int idx = tid; idx < 64 * 128; idx += 256) {
        int m = idx >> 7, k = idx & 127;
        int n = node0 + m;
        float v = 0.f;
        if (n < NN) v = (k < 64) ? h[n * 64 + k] : g_agg[n * 64 + (k - 64)];
        A[m * 129 + k] = v;
    }

    int tx = tid & 15, ty = tid >> 4;
    int m0 = ty * 4;

    float4 acc[4][4];
    #pragma unroll
    for (int i = 0; i < 4; i++)
        #pragma unroll
        for (int j = 0; j < 4; j++) acc[i][j] = make_float4(0.f, 0.f, 0.f, 0.f);

    #pragma unroll 1
    for (int kk = 0; kk < 4; kk++) {
        __syncthreads();  // also orders initial U2/A loads on first iter
        for (int idx = tid; idx < 32 * 256; idx += 256)
            WC[idx] = u1[kk * 32 * 256 + idx];
        __syncthreads();
        #pragma unroll 4
        for (int k = 0; k < 32; k++) {
            float a[4];
            #pragma unroll
            for (int i = 0; i < 4; i++) a[i] = A[(m0 + i) * 129 + kk * 32 + k];
            #pragma unroll
            for (int j = 0; j < 4; j++) {
                float4 w = *(const float4*)&WC[k * 256 + tx * 4 + 64 * j];
                #pragma unroll
                for (int i = 0; i < 4; i++) fma4(acc[i][j], a[i], w);
            }
        }
    }

    // bias + silu -> Hs
    #pragma unroll
    for (int i = 0; i < 4; i++) {
        #pragma unroll
        for (int j = 0; j < 4; j++) {
            float4 bb = *(const float4*)&B1[tx * 4 + 64 * j];
            float4 v = acc[i][j];
            v.x = silu_f(v.x + bb.x); v.y = silu_f(v.y + bb.y);
            v.z = silu_f(v.z + bb.z); v.w = silu_f(v.w + bb.w);
            *(float4*)&Hs[(m0 + i) * 260 + tx * 4 + 64 * j] = v;
        }
    }
    __syncthreads();

    // GEMM2: dh[64,64] = Hs @ U2
    float4 c2[4];
    #pragma unroll
    for (int i = 0; i < 4; i++) c2[i] = make_float4(0.f, 0.f, 0.f, 0.f);

    #pragma unroll 2
    for (int k0 = 0; k0 < 256; k0 += 4) {
        float ha[4][4];
        #pragma unroll
        for (int i = 0; i < 4; i++) {
            float4 tq = *(const float4*)&Hs[(m0 + i) * 260 + k0];
            ha[i][0] = tq.x; ha[i][1] = tq.y; ha[i][2] = tq.z; ha[i][3] = tq.w;
        }
        #pragma unroll
        for (int kk = 0; kk < 4; kk++) {
            float4 w = *(const float4*)&U2[(k0 + kk) * 64 + tx * 4];
            #pragma unroll
            for (int i = 0; i < 4; i++) fma4(c2[i], ha[i][kk], w);
        }
    }

    float4 bb2 = *(const float4*)&B2[tx * 4];
    #pragma unroll
    for (int i = 0; i < 4; i++) {
        int n = node0 + m0 + i;
        if (n < NN) {
            float4 hv = *(const float4*)&h[n * 64 + tx * 4];
            float4 v;
            v.x = hv.x + c2[i].x + bb2.x;
            v.y = hv.y + c2[i].y + bb2.y;
            v.z = hv.z + c2[i].z + bb2.z;
            v.w = hv.w + c2[i].w + bb2.w;
            *(float4*)&g_hnew[n * 64 + tx * 4] = v;
        }
    }
}

// ---------------- K4: per-graph sums + counts ----------------
__global__ void k_stats1(const int* __restrict__ batch) {
    __shared__ float sg[NG * DM];
    __shared__ float scnt[NG];
    int tid = threadIdx.x;
    for (int idx = tid; idx < NG * DM; idx += 256) sg[idx] = 0.f;
    if (tid < NG) scnt[tid] = 0.f;
    __syncthreads();

    int c = tid & 63, r = tid >> 6;
    int base = blockIdx.x * 512;
    for (int i = 0; i < 128; i++) {
        int n = base + r + 4 * i;
        if (n < NN) {
            int g = batch[n];
            atomicAdd(&sg[g * 64 + c], g_hnew[n * 64 + c]);
            if (c == 0) atomicAdd(&scnt[g], 1.f);
        }
    }
    __syncthreads();
    for (int idx = tid; idx < NG * DM; idx += 256) {
        float v = sg[idx];
        if (v != 0.f) atomicAdd(&g_gsum[idx], v);
    }
    if (tid < NG && scnt[tid] != 0.f) atomicAdd(&g_gcnt[tid], scnt[tid]);
}

__global__ void k_mean() {
    int i = blockIdx.x * blockDim.x + threadIdx.x;
    if (i < NG * DM) {
        float cnt = fmaxf(g_gcnt[i >> 6], 1.f);
        g_mean[i] = g_gsum[i] / cnt;
    }
}

// ---------------- K5: per-graph variance sums ----------------
__global__ void k_stats2(const int* __restrict__ batch,
                         const float* __restrict__ alpha) {
    __shared__ float sg[NG * DM];
    int tid = threadIdx.x;
    for (int idx = tid; idx < NG * DM; idx += 256) sg[idx] = 0.f;
    __syncthreads();

    int c = tid & 63, r = tid >> 6;
    float al = alpha[c];
    int base = blockIdx.x * 512;
    for (int i = 0; i < 128; i++) {
        int n = base + r + 4 * i;
        if (n < NN) {
            int g = batch[n];
            float hc = g_hnew[n * 64 + c] - al * g_mean[g * 64 + c];
            atomicAdd(&sg[g * 64 + c], hc * hc);
        }
    }
    __syncthreads();
    for (int idx = tid; idx < NG * DM; idx += 256) {
        float v = sg[idx];
        if (v != 0.f) atomicAdd(&g_gvar[idx], v);
    }
}

__global__ void k_rstd() {
    int i = blockIdx.x * blockDim.x + threadIdx.x;
    if (i < NG * DM) {
        float cnt = fmaxf(g_gcnt[i >> 6], 1.f);
        g_rstd[i] = rsqrtf(g_gvar[i] / cnt + EPSV);
    }
}

// ---------------- K7: final normalize ----------------
__global__ void k_final(const int* __restrict__ batch,
                        const float* __restrict__ wgt,
                        const float* __restrict__ bias,
                        const float* __restrict__ alpha,
                        float* __restrict__ out) {
    int idx = blockIdx.x * blockDim.x + threadIdx.x;
    if (idx < NN * DM) {
        int n = idx >> 6, c = idx & 63;
        int g = batch[n];
        float hc = g_hnew[idx] - alpha[c] * g_mean[g * 64 + c];
        out[idx] = wgt[c] * hc * g_rstd[g * 64 + c] + bias[c];
    }
}

// ---------------- launch ----------------
extern "C" void kernel_launch(void* const* d_in, const int* in_sizes, int n_in,
                              void* d_out, int out_size) {
    const float* h     = (const float*)d_in[0];
    const float* ea    = (const float*)d_in[1];
    const int*   eidx  = (const int*)d_in[2];
    const int*   batch = (const int*)d_in[3];
    const float* mw1   = (const float*)d_in[4];
    const float* mb1   = (const float*)d_in[5];
    const float* mw2   = (const float*)d_in[6];
    const float* mb2   = (const float*)d_in[7];
    const float* uw1   = (const float*)d_in[8];
    const float* ub1   = (const float*)d_in[9];
    const float* uw2   = (const float*)d_in[10];
    const float* ub2   = (const float*)d_in[11];
    const float* gw    = (const float*)d_in[12];
    const float* gb    = (const float*)d_in[13];
    const float* ga    = (const float*)d_in[14];
    float* out = (float*)d_out;

    const int SMEM_PRE  = 20544 * 4;   // 82176
    const int SMEM_EDGE = 43776 * 4;   // 175104
    const int SMEM_NODE = 49792 * 4;   // 199168

    cudaFuncSetAttribute(k_pre,  cudaFuncAttributeMaxDynamicSharedMemorySize, SMEM_PRE);
    cudaFuncSetAttribute(k_edge, cudaFuncAttributeMaxDynamicSharedMemorySize, SMEM_EDGE);
    cudaFuncSetAttribute(k_node, cudaFuncAttributeMaxDynamicSharedMemorySize, SMEM_NODE);

    k_zero<<<4096, 256>>>();
    k_pre<<<(NN + 63) / 64, 256, SMEM_PRE>>>(h, mw1);
    k_edge<<<152, 256, SMEM_EDGE>>>(ea, eidx, mw1, mb1, mw2, mb2);
    k_node<<<(NN + 63) / 64, 256, SMEM_NODE>>>(h, uw1, ub1, uw2, ub2);
    k_stats1<<<(NN + 511) / 512, 256>>>(batch);
    k_mean<<<16, 256>>>();
    k_stats2<<<(NN + 511) / 512, 256>>>(batch, ga);
    k_rstd<<<16, 256>>>();
    k_final<<<(NN * DM + 255) / 256, 256>>>(batch, gw, gb, ga, out);
}

// round 4
// speedup vs baseline: 1.1255x; 1.1255x over previous
#include <cuda_runtime.h>

#define NN 50000
#define NE 800000
#define DM 64
#define DE 32
#define DH 256
#define NG 64
#define EPSV 1e-5f

typedef unsigned long long u64;

// ---------------- scratch ----------------
__device__ __align__(256) float g_Xd[NN * DH];
__device__ __align__(256) float g_Xs[NN * DH];
__device__ __align__(256) float g_agg[NN * DM];
__device__ __align__(256) float g_hnew[NN * DM];
__device__ __align__(256) float g_gsum[NG * DM];
__device__ __align__(256) float g_gvar[NG * DM];   // holds sum of squares
__device__ __align__(256) float g_mean[NG * DM];
__device__ __align__(256) float g_rstd[NG * DM];
__device__ __align__(256) float g_gcnt[NG];

__device__ __forceinline__ float silu_f(float x) { return x / (1.f + __expf(-x)); }

// packed fp32x2 helpers (bit-exact fp32, 2x FFMA rate on sm_103a)
__device__ __forceinline__ u64 pk2(float a) {
    u64 r; asm("mov.b64 %0, {%1, %1};" : "=l"(r) : "f"(a)); return r;
}
__device__ __forceinline__ void f2ma(u64& c, u64 a, u64 b) {
    asm("fma.rn.f32x2 %0, %1, %2, %0;" : "+l"(c) : "l"(a), "l"(b));
}
__device__ __forceinline__ float2 unpk(u64 v) {
    float2 r; asm("mov.b64 {%0, %1}, %2;" : "=f"(r.x), "=f"(r.y) : "l"(v)); return r;
}
__device__ __forceinline__ float4 up4(const ulonglong2& v) {
    float2 a = unpk(v.x), b = unpk(v.y);
    return make_float4(a.x, a.y, b.x, b.y);
}

// ---------------- K0: zero scratch ----------------
__global__ void k_zero() {
    int i = blockIdx.x * blockDim.x + threadIdx.x;
    int stride = gridDim.x * blockDim.x;
    for (int j = i; j < NN * DM; j += stride) g_agg[j] = 0.f;
    if (i < NG * DM) { g_gsum[i] = 0.f; g_gvar[i] = 0.f; }
    if (i < NG) g_gcnt[i] = 0.f;
}

// ---------------- K1: per-node precompute Xd, Xs ----------------
__global__ __launch_bounds__(256, 1) void k_pre(const float* __restrict__ h,
                                                const float* __restrict__ w1) {
    extern __shared__ float sm[];
    float* As = sm;          // 64 x 65
    float* Ws = sm + 4160;   // 64 x 256

    int tid = threadIdx.x;
    int node0 = blockIdx.x * 64;

    for (int idx = tid; idx < 64 * 64; idx += 256) {
        int m = idx >> 6, k = idx & 63;
        int n = node0 + m;
        As[m * 65 + k] = (n < NN) ? h[n * 64 + k] : 0.f;
    }

    int tx = tid & 15, ty = tid >> 4;
    int m0 = ty * 4;

    #pragma unroll 1
    for (int p = 0; p < 2; ++p) {
        __syncthreads();
        for (int idx = tid; idx < 64 * 256; idx += 256)
            Ws[idx] = w1[p * 64 * 256 + idx];
        __syncthreads();

        ulonglong2 acc[4][4];
        #pragma unroll
        for (int i = 0; i < 4; i++)
            #pragma unroll
            for (int j = 0; j < 4; j++) { acc[i][j].x = 0ull; acc[i][j].y = 0ull; }

        #pragma unroll 4
        for (int k = 0; k < 64; k++) {
            u64 a[4];
            #pragma unroll
            for (int i = 0; i < 4; i++) a[i] = pk2(As[(m0 + i) * 65 + k]);
            #pragma unroll
            for (int j = 0; j < 4; j++) {
                ulonglong2 w = *(const ulonglong2*)&Ws[k * 256 + tx * 4 + 64 * j];
                #pragma unroll
                for (int i = 0; i < 4; i++) { f2ma(acc[i][j].x, a[i], w.x); f2ma(acc[i][j].y, a[i], w.y); }
            }
        }

        float* out = p ? g_Xs : g_Xd;
        #pragma unroll
        for (int i = 0; i < 4; i++) {
            int n = node0 + m0 + i;
            if (n < NN) {
                #pragma unroll
                for (int j = 0; j < 4; j++)
                    *(float4*)&out[n * 256 + tx * 4 + 64 * j] = up4(acc[i][j]);
            }
        }
    }
}

// ---------------- K2: edge MLP + scatter-add (persistent, 512 thr) ----------------
__global__ __launch_bounds__(512, 1) void k_edge(const float* __restrict__ ea,
                                                 const int* __restrict__ eidx,
                                                 const float* __restrict__ w1,
                                                 const float* __restrict__ b1,
                                                 const float* __restrict__ w2,
                                                 const float* __restrict__ b2) {
    extern __shared__ float sm[];
    float* W1c = sm;             // 32 x 256  = 8192
    float* W2s = sm + 8192;      // 256 x 64  = 16384
    float* B1  = sm + 24576;     // 256
    float* B2  = sm + 24832;     // 64
    float* EA  = sm + 24896;     // 64 x 33   = 2112
    float* Hs  = sm + 27008;     // 64 x 260  = 16640
    int*   SD  = (int*)(sm + 43648);  // 64
    int*   SS  = (int*)(sm + 43712);  // 64

    int tid = threadIdx.x;
    for (int idx = tid; idx < 32 * 256; idx += 512) W1c[idx] = w1[128 * 256 + idx];
    for (int idx = tid; idx < 256 * 64; idx += 512) W2s[idx] = w2[idx];
    if (tid < 256) B1[tid] = b1[tid];
    if (tid < 64)  B2[tid] = b2[tid];

    int tx = tid & 15, ty = tid >> 4;   // tx: 16 col groups, ty: 32 row pairs
    int m0 = ty * 2;

    for (int t = blockIdx.x; t < NE / 64; t += gridDim.x) {
        int e0 = t * 64;
        __syncthreads();  // guard smem reuse (and initial loads on first tile)

        if (tid < 64) SS[tid] = eidx[e0 + tid];
        else if (tid < 128) SD[tid - 64] = eidx[NE + e0 + tid - 64];
        for (int idx = tid; idx < 64 * 32; idx += 512) {
            int m = idx >> 5, k = idx & 31;
            EA[m * 33 + k] = ea[e0 * 32 + idx];
        }
        __syncthreads();

        // Phase B: gather Xd[dst]+Xs[src] into registers (overlaps GEMM1 below)
        int dn0 = SD[m0], sn0 = SS[m0], dn1 = SD[m0 + 1], sn1 = SS[m0 + 1];
        float4 xsum[2][4];
        #pragma unroll
        for (int j = 0; j < 4; j++) {
            int n = tx * 4 + 64 * j;
            float4 d0 = *(const float4*)&g_Xd[dn0 * 256 + n];
            float4 s0 = *(const float4*)&g_Xs[sn0 * 256 + n];
            float4 d1 = *(const float4*)&g_Xd[dn1 * 256 + n];
            float4 s1 = *(const float4*)&g_Xs[sn1 * 256 + n];
            xsum[0][j] = make_float4(d0.x + s0.x, d0.y + s0.y, d0.z + s0.z, d0.w + s0.w);
            xsum[1][j] = make_float4(d1.x + s1.x, d1.y + s1.y, d1.z + s1.z, d1.w + s1.w);
        }

        // Phase C: GEMM1  C[64,256] = EA[64,32] @ W1c[32,256]
        ulonglong2 acc[2][4];
        #pragma unroll
        for (int i = 0; i < 2; i++)
            #pragma unroll
            for (int j = 0; j < 4; j++) { acc[i][j].x = 0ull; acc[i][j].y = 0ull; }

        #pragma unroll 4
        for (int k = 0; k < 32; k++) {
            u64 a0 = pk2(EA[m0 * 33 + k]);
            u64 a1 = pk2(EA[(m0 + 1) * 33 + k]);
            #pragma unroll
            for (int j = 0; j < 4; j++) {
                ulonglong2 w = *(const ulonglong2*)&W1c[k * 256 + tx * 4 + 64 * j];
                f2ma(acc[0][j].x, a0, w.x); f2ma(acc[0][j].y, a0, w.y);
                f2ma(acc[1][j].x, a1, w.x); f2ma(acc[1][j].y, a1, w.y);
            }
        }

        // Phase D: hidden = silu(acc + xsum + b1) -> Hs
        #pragma unroll
        for (int i = 0; i < 2; i++) {
            #pragma unroll
            for (int j = 0; j < 4; j++) {
                int n = tx * 4 + 64 * j;
                float4 a = up4(acc[i][j]);
                float4 bb = *(const float4*)&B1[n];
                float4 v;
                v.x = silu_f(a.x + xsum[i][j].x + bb.x);
                v.y = silu_f(a.y + xsum[i][j].y + bb.y);
                v.z = silu_f(a.z + xsum[i][j].z + bb.z);
                v.w = silu_f(a.w + xsum[i][j].w + bb.w);
                *(float4*)&Hs[(m0 + i) * 260 + n] = v;
            }
        }
        __syncthreads();

        // Phase E: GEMM2  m[64,64] = Hs[64,256] @ W2[256,64]
        ulonglong2 c2[2];
        c2[0].x = c2[0].y = c2[1].x = c2[1].y = 0ull;

        #pragma unroll 2
        for (int k0 = 0; k0 < 256; k0 += 4) {
            float4 q0 = *(const float4*)&Hs[m0 * 260 + k0];
            float4 q1 = *(const float4*)&Hs[(m0 + 1) * 260 + k0];
            float a0s[4] = {q0.x, q0.y, q0.z, q0.w};
            float a1s[4] = {q1.x, q1.y, q1.z, q1.w};
            #pragma unroll
            for (int kk = 0; kk < 4; kk++) {
                ulonglong2 w = *(const ulonglong2*)&W2s[(k0 + kk) * 64 + tx * 4];
                u64 a0 = pk2(a0s[kk]), a1 = pk2(a1s[kk]);
                f2ma(c2[0].x, a0, w.x); f2ma(c2[0].y, a0, w.y);
                f2ma(c2[1].x, a1, w.x); f2ma(c2[1].y, a1, w.y);
            }
        }

        float4 bb2 = *(const float4*)&B2[tx * 4];
        #pragma unroll
        for (int i = 0; i < 2; i++) {
            int dn = (i == 0) ? dn0 : dn1;
            float4 a = up4(c2[i]);
            float4 v = make_float4(a.x + bb2.x, a.y + bb2.y, a.z + bb2.z, a.w + bb2.w);
            float* p = &g_agg[dn * 64 + tx * 4];
            asm volatile("red.global.add.v4.f32 [%0], {%1, %2, %3, %4};"
                         :: "l"(p), "f"(v.x), "f"(v.y), "f"(v.z), "f"(v.w)
                         : "memory");
        }
    }
}

// ---------------- K3: node update MLP (512 thr) ----------------
__global__ __launch_bounds__(512, 1) void k_node(const float* __restrict__ h,
                                                 const float* __restrict__ u1,
                                                 const float* __restrict__ ub1,
                                                 const float* __restrict__ u2,
                                                 const float* __restrict__ ub2) {
    extern __shared__ float sm[];
    float* U2 = sm;              // 256 x 64 = 16384
    float* WC = sm + 16384;      // 32 x 256 = 8192
    float* B1 = sm + 24576;      // 256
    float* B2 = sm + 24832;      // 64
    float* A  = sm + 24896;      // 64 x 129 = 8256
    float* Hs = sm + 33152;      // 64 x 260 = 16640

    int tid = threadIdx.x;
    int node0 = blockIdx.x * 64;

    for (int idx = tid; idx < 256 * 64; idx += 512) U2[idx] = u2[idx];
    if (tid < 256) B1[tid] = ub1[tid];
    if (tid < 64)  B2[tid] = ub2[tid];

    for (int idx = tid; idx < 64 * 128; idx += 512) {
        int m = idx >> 7, k = idx & 127;
        int n = node0 + m;
        float v = 0.f;
        if (n < NN) v = (k < 64) ? h[n * 64 + k] : g_agg[n * 64 + (k - 64)];
        A[m * 129 + k] = v;
    }

    int tx = tid & 15, ty = tid >> 4;
    int m0 = ty * 2;

    ulonglong2 acc[2][4];
    #pragma unroll
    for (int i = 0; i < 2; i++)
        #pragma unroll
        for (int j = 0; j < 4; j++) { acc[i][j].x = 0ull; acc[i][j].y = 0ull; }

    #pragma unroll 1
    for (int kk = 0; kk < 4; kk++) {
        __syncthreads();
        for (int idx = tid; idx < 32 * 256; idx += 512)
            WC[idx] = u1[kk * 32 * 256 + idx];
        __syncthreads();
        #pragma unroll 4
        for (int k = 0; k < 32; k++) {
            u64 a0 = pk2(A[m0 * 129 + kk * 32 + k]);
            u64 a1 = pk2(A[(m0 + 1) * 129 + kk * 32 + k]);
            #pragma unroll
            for (int j = 0; j < 4; j++) {
                ulonglong2 w = *(const ulonglong2*)&WC[k * 256 + tx * 4 + 64 * j];
                f2ma(acc[0][j].x, a0, w.x); f2ma(acc[0][j].y, a0, w.y);
                f2ma(acc[1][j].x, a1, w.x); f2ma(acc[1][j].y, a1, w.y);
            }
        }
    }

    #pragma unroll
    for (int i = 0; i < 2; i++) {
        #pragma unroll
        for (int j = 0; j < 4; j++) {
            int n = tx * 4 + 64 * j;
            float4 a = up4(acc[i][j]);
            float4 bb = *(const float4*)&B1[n];
            float4 v;
            v.x = silu_f(a.x + bb.x); v.y = silu_f(a.y + bb.y);
            v.z = silu_f(a.z + bb.z); v.w = silu_f(a.w + bb.w);
            *(float4*)&Hs[(m0 + i) * 260 + n] = v;
        }
    }
    __syncthreads();

    ulonglong2 c2[2];
    c2[0].x = c2[0].y = c2[1].x = c2[1].y = 0ull;

    #pragma unroll 2
    for (int k0 = 0; k0 < 256; k0 += 4) {
        float4 q0 = *(const float4*)&Hs[m0 * 260 + k0];
        float4 q1 = *(const float4*)&Hs[(m0 + 1) * 260 + k0];
        float a0s[4] = {q0.x, q0.y, q0.z, q0.w};
        float a1s[4] = {q1.x, q1.y, q1.z, q1.w};
        #pragma unroll
        for (int kk = 0; kk < 4; kk++) {
            ulonglong2 w = *(const ulonglong2*)&U2[(k0 + kk) * 64 + tx * 4];
            u64 a0 = pk2(a0s[kk]), a1 = pk2(a1s[kk]);
            f2ma(c2[0].x, a0, w.x); f2ma(c2[0].y, a0, w.y);
            f2ma(c2[1].x, a1, w.x); f2ma(c2[1].y, a1, w.y);
        }
    }

    float4 bb2 = *(const float4*)&B2[tx * 4];
    #pragma unroll
    for (int i = 0; i < 2; i++) {
        int n = node0 + m0 + i;
        if (n < NN) {
            float4 hv = *(const float4*)&h[n * 64 + tx * 4];
            float4 a = up4(c2[i]);
            float4 v;
            v.x = hv.x + a.x + bb2.x;
            v.y = hv.y + a.y + bb2.y;
            v.z = hv.z + a.z + bb2.z;
            v.w = hv.w + a.w + bb2.w;
            *(float4*)&g_hnew[n * 64 + tx * 4] = v;
        }
    }
}

// ---------------- K4: per-graph sum, sumsq, count (single pass) ----------------
__global__ void k_stats(const int* __restrict__ batch) {
    __shared__ float ss[NG * DM];
    __shared__ float sq[NG * DM];
    __shared__ float scnt[NG];
    int tid = threadIdx.x;
    for (int idx = tid; idx < NG * DM; idx += 256) { ss[idx] = 0.f; sq[idx] = 0.f; }
    if (tid < NG) scnt[tid] = 0.f;
    __syncthreads();

    int c = tid & 63, r = tid >> 6;
    int base = blockIdx.x * 512;
    for (int i = 0; i < 128; i++) {
        int n = base + r + 4 * i;
        if (n < NN) {
            int g = batch[n];
            float v = g_hnew[n * 64 + c];
            atomicAdd(&ss[g * 64 + c], v);
            atomicAdd(&sq[g * 64 + c], v * v);
            if (c == 0) atomicAdd(&scnt[g], 1.f);
        }
    }
    __syncthreads();
    for (int idx = tid; idx < NG * DM; idx += 256) {
        if (ss[idx] != 0.f) atomicAdd(&g_gsum[idx], ss[idx]);
        if (sq[idx] != 0.f) atomicAdd(&g_gvar[idx], sq[idx]);
    }
    if (tid < NG && scnt[tid] != 0.f) atomicAdd(&g_gcnt[tid], scnt[tid]);
}

// ---------------- K5: mean + rstd from raw moments ----------------
// var(h - a*m) = E[h^2] - a*(2-a)*m^2   (exact identity since m = E[h])
__global__ void k_mv(const float* __restrict__ alpha) {
    int i = blockIdx.x * blockDim.x + threadIdx.x;
    if (i < NG * DM) {
        int c = i & 63;
        float cnt = fmaxf(g_gcnt[i >> 6], 1.f);
        float m = g_gsum[i] / cnt;
        float a = alpha[c];
        float var = g_gvar[i] / cnt - a * (2.f - a) * m * m;
        g_mean[i] = m;
        g_rstd[i] = rsqrtf(var + EPSV);
    }
}

// ---------------- K6: final normalize ----------------
__global__ void k_final(const int* __restrict__ batch,
                        const float* __restrict__ wgt,
                        const float* __restrict__ bias,
                        const float* __restrict__ alpha,
                        float* __restrict__ out) {
    int idx = blockIdx.x * blockDim.x + threadIdx.x;
    if (idx < NN * DM) {
        int n = idx >> 6, c = idx & 63;
        int g = batch[n];
        float hc = g_hnew[idx] - alpha[c] * g_mean[g * 64 + c];
        out[idx] = wgt[c] * hc * g_rstd[g * 64 + c] + bias[c];
    }
}

// ---------------- launch ----------------
extern "C" void kernel_launch(void* const* d_in, const int* in_sizes, int n_in,
                              void* d_out, int out_size) {
    const float* h     = (const float*)d_in[0];
    const float* ea    = (const float*)d_in[1];
    const int*   eidx  = (const int*)d_in[2];
    const int*   batch = (const int*)d_in[3];
    const float* mw1   = (const float*)d_in[4];
    const float* mb1   = (const float*)d_in[5];
    const float* mw2   = (const float*)d_in[6];
    const float* mb2   = (const float*)d_in[7];
    const float* uw1   = (const float*)d_in[8];
    const float* ub1   = (const float*)d_in[9];
    const float* uw2   = (const float*)d_in[10];
    const float* ub2   = (const float*)d_in[11];
    const float* gw    = (const float*)d_in[12];
    const float* gb    = (const float*)d_in[13];
    const float* ga    = (const float*)d_in[14];
    float* out = (float*)d_out;

    const int SMEM_PRE  = 20544 * 4;   // 82176
    const int SMEM_EDGE = 43776 * 4;   // 175104
    const int SMEM_NODE = 49792 * 4;   // 199168

    cudaFuncSetAttribute(k_pre,  cudaFuncAttributeMaxDynamicSharedMemorySize, SMEM_PRE);
    cudaFuncSetAttribute(k_edge, cudaFuncAttributeMaxDynamicSharedMemorySize, SMEM_EDGE);
    cudaFuncSetAttribute(k_node, cudaFuncAttributeMaxDynamicSharedMemorySize, SMEM_NODE);

    k_zero<<<4096, 256>>>();
    k_pre<<<(NN + 63) / 64, 256, SMEM_PRE>>>(h, mw1);
    k_edge<<<148, 512, SMEM_EDGE>>>(ea, eidx, mw1, mb1, mw2, mb2);
    k_node<<<(NN + 63) / 64, 512, SMEM_NODE>>>(h, uw1, ub1, uw2, ub2);
    k_stats<<<(NN + 511) / 512, 256>>>(batch);
    k_mv<<<16, 256>>>(ga);
    k_final<<<(NN * DM + 255) / 256, 256>>>(batch, gw, gb, ga, out);
}

// round 5
// speedup vs baseline: 1.6324x; 1.4503x over previous
#include <cuda_runtime.h>

#define NN 50000
#define NE 800000
#define DM 64
#define DE 32
#define DH 256
#define NG 64
#define EPSV 1e-5f
#define GRID_E 152
#define NTILES 12500

typedef unsigned long long u64;

// ---------------- scratch ----------------
__device__ __align__(256) float g_Xd[NN * DH];
__device__ __align__(256) float g_Xs[NN * DH];
__device__ __align__(256) float g_agg[NN * DM];
__device__ __align__(256) float g_hnew[NN * DM];
__device__ __align__(256) float g_gsum[NG * DM];
__device__ __align__(256) float g_gvar[NG * DM];   // sum of squares
__device__ __align__(256) float g_mean[NG * DM];
__device__ __align__(256) float g_rstd[NG * DM];
__device__ __align__(256) float g_gcnt[NG];

__device__ __forceinline__ float silu_f(float x) { return x / (1.f + __expf(-x)); }

__device__ __forceinline__ u64 pk2(float a) {
    u64 r; asm("mov.b64 %0, {%1, %1};" : "=l"(r) : "f"(a)); return r;
}
__device__ __forceinline__ u64 pkf2(float lo, float hi) {
    u64 r; asm("mov.b64 %0, {%1, %2};" : "=l"(r) : "f"(lo), "f"(hi)); return r;
}
__device__ __forceinline__ void f2ma(u64& c, u64 a, u64 b) {
    asm("fma.rn.f32x2 %0, %1, %2, %0;" : "+l"(c) : "l"(a), "l"(b));
}
__device__ __forceinline__ float2 unpk(u64 v) {
    float2 r; asm("mov.b64 {%0, %1}, %2;" : "=f"(r.x), "=f"(r.y) : "l"(v)); return r;
}
__device__ __forceinline__ float4 up4(const ulonglong2& v) {
    float2 a = unpk(v.x), b = unpk(v.y);
    return make_float4(a.x, a.y, b.x, b.y);
}

// ---------------- K0: zero scratch ----------------
__global__ void k_zero() {
    int i = blockIdx.x * blockDim.x + threadIdx.x;
    int stride = gridDim.x * blockDim.x;
    for (int j = i; j < NN * DM; j += stride) g_agg[j] = 0.f;
    if (i < NG * DM) { g_gsum[i] = 0.f; g_gvar[i] = 0.f; }
    if (i < NG) g_gcnt[i] = 0.f;
}

// ---------------- K1: Xd = h @ W1[0:64], Xs = h @ W1[64:128] ----------------
// 512 thr, warp = 8 rows x 128 cols (R=8).
__global__ __launch_bounds__(512, 1) void k_pre(const float* __restrict__ h,
                                                const float* __restrict__ w1) {
    extern __shared__ float sm[];
    float* A  = sm;          // 64 x 68 = 4352
    float* Ws = sm + 4352;   // 64 x 256 = 16384

    int tid = threadIdx.x, lane = tid & 31, wid = tid >> 5;
    int rowGrp = wid & 7, colHalf = wid >> 3;
    int m0 = rowGrp * 8;
    int nc = colHalf * 128 + lane * 4;
    int node0 = blockIdx.x * 64;

    for (int idx = tid; idx < 64 * 64; idx += 512) {
        int m = idx >> 6, k = idx & 63;
        int n = node0 + m;
        A[m * 68 + k] = (n < NN) ? h[n * 64 + k] : 0.f;
    }

    #pragma unroll 1
    for (int p = 0; p < 2; ++p) {
        __syncthreads();
        for (int idx = tid; idx < 64 * 256; idx += 512)
            Ws[idx] = w1[p * 64 * 256 + idx];
        __syncthreads();

        ulonglong2 acc[8];
        #pragma unroll
        for (int r = 0; r < 8; r++) { acc[r].x = 0ull; acc[r].y = 0ull; }

        #pragma unroll 2
        for (int kc = 0; kc < 64; kc += 4) {
            float a[8][4];
            #pragma unroll
            for (int r = 0; r < 8; r++)
                *(float4*)a[r] = *(const float4*)&A[(m0 + r) * 68 + kc];
            #pragma unroll
            for (int kk = 0; kk < 4; kk++) {
                ulonglong2 w = *(const ulonglong2*)&Ws[(kc + kk) * 256 + nc];
                #pragma unroll
                for (int r = 0; r < 8; r++) {
                    u64 av = pk2(a[r][kk]);
                    f2ma(acc[r].x, av, w.x);
                    f2ma(acc[r].y, av, w.y);
                }
            }
        }

        float* out = p ? g_Xs : g_Xd;
        #pragma unroll
        for (int r = 0; r < 8; r++) {
            int n = node0 + m0 + r;
            if (n < NN) *(float4*)&out[n * 256 + nc] = up4(acc[r]);
        }
    }
}

// ---------------- K2: edge MLP + scatter (persistent, 512 thr, R=8) ----------------
__global__ __launch_bounds__(512, 1) void k_edge(const float* __restrict__ ea,
                                                 const int* __restrict__ eidx,
                                                 const float* __restrict__ w1,
                                                 const float* __restrict__ b1,
                                                 const float* __restrict__ w2,
                                                 const float* __restrict__ b2) {
    extern __shared__ float sm[];
    float* W1c = sm;                      // 32 x 256 = 8192
    float* W2s = sm + 8192;               // 256 x 64 = 16384
    float* B1  = sm + 24576;              // 256
    float* B2  = sm + 24832;              // 64
    float* EA0 = sm + 24896;              // 2 x (64 x 36) = 4608
    int*   SS0 = (int*)(sm + 29504);      // 2 x 64
    int*   SD0 = (int*)(sm + 29632);      // 2 x 64
    float* Hs  = sm + 29760;              // 64 x 260 = 16640
    float* Par = sm + 46400;              // 64 x 66 = 4224   (total 50624 f = 202,496 B)

    int tid = threadIdx.x, lane = tid & 31, wid = tid >> 5;
    int rowGrp = wid & 7, colHalf = wid >> 3;
    int m0 = rowGrp * 8;
    int nc = colHalf * 128 + lane * 4;

    for (int idx = tid; idx < 32 * 256; idx += 512) W1c[idx] = w1[128 * 256 + idx];
    for (int idx = tid; idx < 256 * 64; idx += 512) W2s[idx] = w2[idx];
    if (tid < 256) B1[tid] = b1[tid];
    if (tid < 64)  B2[tid] = b2[tid];

    // preload first tile into buffer 0
    {
        int e0 = blockIdx.x * 64;
        float4 pf = *(const float4*)&ea[e0 * 32 + tid * 4];
        int m = tid >> 3, k = (tid & 7) * 4;
        *(float4*)&EA0[m * 36 + k] = pf;
        if (tid < 64) SS0[tid] = eidx[e0 + tid];
        else if (tid < 128) SD0[tid - 64] = eidx[NE + e0 + tid - 64];
    }
    __syncthreads();

    int p = 0;
    for (int t = blockIdx.x; t < NTILES; t += GRID_E) {
        float* EA = EA0 + p * 2304;
        int*   SS = SS0 + p * 64;
        int*   SD = SD0 + p * 64;

        // issue prefetch of next tile (registers; STS deferred past GEMM1)
        int t2 = t + GRID_E;
        bool havepf = (t2 < NTILES);
        float4 pf; int pfi = 0;
        if (havepf) {
            int e2 = t2 * 64;
            pf = *(const float4*)&ea[e2 * 32 + tid * 4];
            if (tid < 64) pfi = eidx[e2 + tid];
            else if (tid < 128) pfi = eidx[NE + e2 + tid - 64];
        }

        // init acc with Xd[dst] + Xs[src] gather (overlaps GEMM1 weight loads)
        ulonglong2 acc[8];
        #pragma unroll
        for (int r = 0; r < 8; r++) {
            int dn = SD[m0 + r], sn = SS[m0 + r];
            float4 xd = *(const float4*)&g_Xd[dn * 256 + nc];
            float4 xs = *(const float4*)&g_Xs[sn * 256 + nc];
            acc[r].x = pkf2(xd.x + xs.x, xd.y + xs.y);
            acc[r].y = pkf2(xd.z + xs.z, xd.w + xs.w);
        }

        // GEMM1: += EA[64,32] @ W1c[32,256]
        #pragma unroll 2
        for (int kc = 0; kc < 32; kc += 4) {
            float a[8][4];
            #pragma unroll
            for (int r = 0; r < 8; r++)
                *(float4*)a[r] = *(const float4*)&EA[(m0 + r) * 36 + kc];
            #pragma unroll
            for (int kk = 0; kk < 4; kk++) {
                ulonglong2 w = *(const ulonglong2*)&W1c[(kc + kk) * 256 + nc];
                #pragma unroll
                for (int r = 0; r < 8; r++) {
                    u64 av = pk2(a[r][kk]);
                    f2ma(acc[r].x, av, w.x);
                    f2ma(acc[r].y, av, w.y);
                }
            }
        }

        // store prefetched tile into other buffer
        if (havepf) {
            float* EAn = EA0 + (p ^ 1) * 2304;
            int m = tid >> 3, k = (tid & 7) * 4;
            *(float4*)&EAn[m * 36 + k] = pf;
            if (tid < 64) SS0[(p ^ 1) * 64 + tid] = pfi;
            else if (tid < 128) SD0[(p ^ 1) * 64 + tid - 64] = pfi;
        }

        // silu(acc + b1) -> Hs (warp-private region)
        float4 bb = *(const float4*)&B1[nc];
        #pragma unroll
        for (int r = 0; r < 8; r++) {
            float2 lo = unpk(acc[r].x), hi = unpk(acc[r].y);
            float4 v;
            v.x = silu_f(lo.x + bb.x); v.y = silu_f(lo.y + bb.y);
            v.z = silu_f(hi.x + bb.z); v.w = silu_f(hi.y + bb.w);
            *(float4*)&Hs[(m0 + r) * 260 + nc] = v;
        }
        __syncwarp();

        // GEMM2 (k-split by colHalf): m[64,64] = Hs[64,256] @ W2[256,64]
        u64 acc2[8];
        u64 binit = colHalf ? 0ull : pkf2(B2[lane * 2], B2[lane * 2 + 1]);
        #pragma unroll
        for (int r = 0; r < 8; r++) acc2[r] = binit;
        int kb = colHalf * 128;
        #pragma unroll 2
        for (int kc = 0; kc < 128; kc += 4) {
            float hq[8][4];
            #pragma unroll
            for (int r = 0; r < 8; r++)
                *(float4*)hq[r] = *(const float4*)&Hs[(m0 + r) * 260 + kb + kc];
            #pragma unroll
            for (int kk = 0; kk < 4; kk++) {
                u64 w = *(const u64*)&W2s[(kb + kc + kk) * 64 + lane * 2];
                #pragma unroll
                for (int r = 0; r < 8; r++) f2ma(acc2[r], pk2(hq[r][kk]), w);
            }
        }

        // combine k-split halves via Par, then scatter
        if (colHalf == 1) {
            #pragma unroll
            for (int r = 0; r < 8; r++)
                *(u64*)&Par[(m0 + r) * 66 + lane * 2] = acc2[r];
        }
        asm volatile("bar.sync %0, 64;" :: "r"(1 + rowGrp) : "memory");
        if (colHalf == 0) {
            #pragma unroll
            for (int r = 0; r < 8; r++) {
                float2 a0 = unpk(acc2[r]);
                float2 b0 = *(const float2*)&Par[(m0 + r) * 66 + lane * 2];
                float vx = a0.x + b0.x, vy = a0.y + b0.y;
                int dn = SD[m0 + r];
                float* pp = &g_agg[dn * 64 + lane * 2];
                asm volatile("red.global.add.v2.f32 [%0], {%1, %2};"
                             :: "l"(pp), "f"(vx), "f"(vy) : "memory");
            }
        }
        __syncthreads();
        p ^= 1;
    }
}

// ---------------- K3: node update MLP (512 thr, R=8) ----------------
__global__ __launch_bounds__(512, 1) void k_node(const float* __restrict__ h,
                                                 const float* __restrict__ u1,
                                                 const float* __restrict__ ub1,
                                                 const float* __restrict__ u2,
                                                 const float* __restrict__ ub2) {
    extern __shared__ float sm[];
    float* U2 = sm;             // 256 x 64 = 16384
    float* WC = sm + 16384;     // 32 x 256 = 8192 (streamed)
    float* B1 = sm + 24576;     // 256
    float* B2 = sm + 24832;     // 64
    float* A  = sm + 24896;     // 64 x 132 = 8448
    float* Hs = sm + 33344;     // 64 x 260 = 16640
    float* Par= sm + 49984;     // 64 x 66 = 4224   (total 54208 f = 216,832 B)

    int tid = threadIdx.x, lane = tid & 31, wid = tid >> 5;
    int rowGrp = wid & 7, colHalf = wid >> 3;
    int m0 = rowGrp * 8;
    int nc = colHalf * 128 + lane * 4;
    int node0 = blockIdx.x * 64;

    for (int idx = tid; idx < 256 * 64; idx += 512) U2[idx] = u2[idx];
    if (tid < 256) B1[tid] = ub1[tid];
    if (tid < 64)  B2[tid] = ub2[tid];

    for (int idx = tid; idx < 64 * 128; idx += 512) {
        int m = idx >> 7, k = idx & 127;
        int n = node0 + m;
        float v = 0.f;
        if (n < NN) v = (k < 64) ? h[n * 64 + k] : g_agg[n * 64 + (k - 64)];
        A[m * 132 + k] = v;
    }
    __syncthreads();

    ulonglong2 acc[8];
    {
        float4 bb = *(const float4*)&B1[nc];
        #pragma unroll
        for (int r = 0; r < 8; r++) {
            acc[r].x = pkf2(bb.x, bb.y);
            acc[r].y = pkf2(bb.z, bb.w);
        }
    }

    #pragma unroll 1
    for (int c = 0; c < 4; c++) {
        for (int idx = tid; idx < 32 * 256; idx += 512)
            WC[idx] = u1[c * 32 * 256 + idx];
        __syncthreads();
        int kb = c * 32;
        #pragma unroll 2
        for (int kc = 0; kc < 32; kc += 4) {
            float a[8][4];
            #pragma unroll
            for (int r = 0; r < 8; r++)
                *(float4*)a[r] = *(const float4*)&A[(m0 + r) * 132 + kb + kc];
            #pragma unroll
            for (int kk = 0; kk < 4; kk++) {
                ulonglong2 w = *(const ulonglong2*)&WC[(kc + kk) * 256 + nc];
                #pragma unroll
                for (int r = 0; r < 8; r++) {
                    u64 av = pk2(a[r][kk]);
                    f2ma(acc[r].x, av, w.x);
                    f2ma(acc[r].y, av, w.y);
                }
            }
        }
        __syncthreads();
    }

    // silu -> Hs (bias already in acc)
    #pragma unroll
    for (int r = 0; r < 8; r++) {
        float2 lo = unpk(acc[r].x), hi = unpk(acc[r].y);
        float4 v;
        v.x = silu_f(lo.x); v.y = silu_f(lo.y);
        v.z = silu_f(hi.x); v.w = silu_f(hi.y);
        *(float4*)&Hs[(m0 + r) * 260 + nc] = v;
    }
    __syncwarp();

    // GEMM2 (k-split): dh = Hs @ U2 ; out = h + dh + b2
    u64 acc2[8];
    #pragma unroll
    for (int r = 0; r < 8; r++) {
        if (colHalf == 0) {
            int n = node0 + m0 + r;
            float2 hv = make_float2(0.f, 0.f);
            if (n < NN) hv = *(const float2*)&h[n * 64 + lane * 2];
            acc2[r] = pkf2(hv.x + B2[lane * 2], hv.y + B2[lane * 2 + 1]);
        } else acc2[r] = 0ull;
    }
    int kb = colHalf * 128;
    #pragma unroll 2
    for (int kc = 0; kc < 128; kc += 4) {
        float hq[8][4];
        #pragma unroll
        for (int r = 0; r < 8; r++)
            *(float4*)hq[r] = *(const float4*)&Hs[(m0 + r) * 260 + kb + kc];
        #pragma unroll
        for (int kk = 0; kk < 4; kk++) {
            u64 w = *(const u64*)&U2[(kb + kc + kk) * 64 + lane * 2];
            #pragma unroll
            for (int r = 0; r < 8; r++) f2ma(acc2[r], pk2(hq[r][kk]), w);
        }
    }

    if (colHalf == 1) {
        #pragma unroll
        for (int r = 0; r < 8; r++)
            *(u64*)&Par[(m0 + r) * 66 + lane * 2] = acc2[r];
    }
    asm volatile("bar.sync %0, 64;" :: "r"(1 + rowGrp) : "memory");
    if (colHalf == 0) {
        #pragma unroll
        for (int r = 0; r < 8; r++) {
            int n = node0 + m0 + r;
            if (n < NN) {
                float2 a0 = unpk(acc2[r]);
                float2 b0 = *(const float2*)&Par[(m0 + r) * 66 + lane * 2];
                float2 v = make_float2(a0.x + b0.x, a0.y + b0.y);
                *(float2*)&g_hnew[n * 64 + lane * 2] = v;
            }
        }
    }
}

// ---------------- K4: per-graph sum, sumsq, count (single pass) ----------------
__global__ void k_stats(const int* __restrict__ batch) {
    __shared__ float ss[NG * DM];
    __shared__ float sq[NG * DM];
    __shared__ float scnt[NG];
    int tid = threadIdx.x;
    for (int idx = tid; idx < NG * DM; idx += 256) { ss[idx] = 0.f; sq[idx] = 0.f; }
    if (tid < NG) scnt[tid] = 0.f;
    __syncthreads();

    int c = tid & 63, r = tid >> 6;
    int base = blockIdx.x * 512;
    for (int i = 0; i < 128; i++) {
        int n = base + r + 4 * i;
        if (n < NN) {
            int g = batch[n];
            float v = g_hnew[n * 64 + c];
            atomicAdd(&ss[g * 64 + c], v);
            atomicAdd(&sq[g * 64 + c], v * v);
            if (c == 0) atomicAdd(&scnt[g], 1.f);
        }
    }
    __syncthreads();
    for (int idx = tid; idx < NG * DM; idx += 256) {
        if (ss[idx] != 0.f) atomicAdd(&g_gsum[idx], ss[idx]);
        if (sq[idx] != 0.f) atomicAdd(&g_gvar[idx], sq[idx]);
    }
    if (tid < NG && scnt[tid] != 0.f) atomicAdd(&g_gcnt[tid], scnt[tid]);
}

// ---------------- K5: mean + rstd ----------------
// var(h - a*m) = E[h^2] - a*(2-a)*m^2
__global__ void k_mv(const float* __restrict__ alpha) {
    int i = blockIdx.x * blockDim.x + threadIdx.x;
    if (i < NG * DM) {
        int c = i & 63;
        float cnt = fmaxf(g_gcnt[i >> 6], 1.f);
        float m = g_gsum[i] / cnt;
        float a = alpha[c];
        float var = g_gvar[i] / cnt - a * (2.f - a) * m * m;
        g_mean[i] = m;
        g_rstd[i] = rsqrtf(var + EPSV);
    }
}

// ---------------- K6: final normalize ----------------
__global__ void k_final(const int* __restrict__ batch,
                        const float* __restrict__ wgt,
                        const float* __restrict__ bias,
                        const float* __restrict__ alpha,
                        float* __restrict__ out) {
    int idx = blockIdx.x * blockDim.x + threadIdx.x;
    if (idx < NN * DM) {
        int n = idx >> 6, c = idx & 63;
        int g = batch[n];
        float hc = g_hnew[idx] - alpha[c] * g_mean[g * 64 + c];
        out[idx] = wgt[c] * hc * g_rstd[g * 64 + c] + bias[c];
    }
}

// ---------------- launch ----------------
extern "C" void kernel_launch(void* const* d_in, const int* in_sizes, int n_in,
                              void* d_out, int out_size) {
    const float* h     = (const float*)d_in[0];
    const float* ea    = (const float*)d_in[1];
    const int*   eidx  = (const int*)d_in[2];
    const int*   batch = (const int*)d_in[3];
    const float* mw1   = (const float*)d_in[4];
    const float* mb1   = (const float*)d_in[5];
    const float* mw2   = (const float*)d_in[6];
    const float* mb2   = (const float*)d_in[7];
    const float* uw1   = (const float*)d_in[8];
    const float* ub1   = (const float*)d_in[9];
    const float* uw2   = (const float*)d_in[10];
    const float* ub2   = (const float*)d_in[11];
    const float* gw    = (const float*)d_in[12];
    const float* gb    = (const float*)d_in[13];
    const float* ga    = (const float*)d_in[14];
    float* out = (float*)d_out;

    const int SMEM_PRE  = 20736 * 4;   // 82,944
    const int SMEM_EDGE = 50624 * 4;   // 202,496
    const int SMEM_NODE = 54208 * 4;   // 216,832

    cudaFuncSetAttribute(k_pre,  cudaFuncAttributeMaxDynamicSharedMemorySize, SMEM_PRE);
    cudaFuncSetAttribute(k_edge, cudaFuncAttributeMaxDynamicSharedMemorySize, SMEM_EDGE);
    cudaFuncSetAttribute(k_node, cudaFuncAttributeMaxDynamicSharedMemorySize, SMEM_NODE);

    k_zero<<<4096, 256>>>();
    k_pre<<<(NN + 63) / 64, 512, SMEM_PRE>>>(h, mw1);
    k_edge<<<GRID_E, 512, SMEM_EDGE>>>(ea, eidx, mw1, mb1, mw2, mb2);
    k_node<<<(NN + 63) / 64, 512, SMEM_NODE>>>(h, uw1, ub1, uw2, ub2);
    k_stats<<<(NN + 511) / 512, 256>>>(batch);
    k_mv<<<16, 256>>>(ga);
    k_final<<<(NN * DM + 255) / 256, 256>>>(batch, gw, gb, ga, out);
}